// round 7
// baseline (speedup 1.0000x reference)
#include <cuda_runtime.h>
#include <math.h>

#define NPROP 1000
#define NCLS  91
#define TOPK  100
#define NMAX  1024
#define MCAP  256          /* fast bitmask-NMS path capacity */
#define BLK   256
#define SCORE_TH 0.05f
#define NMS_TH   0.5f
#define MIN_SIZE 1.0f
#define BBOX_CLIP 4.1351665567423f   /* log(1000/16) */

// scratch: per-class candidate lists + counters, proposal geometry
__device__ unsigned long long g_list[NCLS * NMAX];
__device__ int    g_cnt[NCLS];           // zero-init at load; each launch re-zeroes
__device__ float4 g_prop[NPROP];         // w, h, cx, cy

__device__ __forceinline__ float read_dim(const void* p) {
    int iv = *(const int*)p;
    if (iv >= 1 && iv <= 100000) return (float)iv;        // int32 / int64 low word
    float fv = __int_as_float(iv);
    if (fv >= 1.0f && fv <= 100000.0f) return fv;          // float32
    return (float)iv;
}

// ---- kernel A: softmax + score filter + per-class compaction (warp per row) ----
__global__ void filter_kernel(const float* __restrict__ class_logit,
                              const float* __restrict__ proposal)
{
    const int gtid = blockIdx.x * blockDim.x + threadIdx.x;
    const int row  = gtid >> 5;
    const int lane = gtid & 31;
    if (row >= NPROP) return;
    const float* r = class_logit + row * NCLS;

    // lanes cover classes {lane, lane+32, lane+64}; c=0 is background (skipped)
    const float l0 = r[lane];
    const float l1 = r[lane + 32];
    const float l2 = (lane + 64 < NCLS) ? r[lane + 64] : -3.4e38f;

    float m = fmaxf(l0, fmaxf(l1, l2));
    #pragma unroll
    for (int o = 16; o; o >>= 1) m = fmaxf(m, __shfl_xor_sync(0xffffffffu, m, o));

    const float e0 = expf(l0 - m);
    const float e1 = expf(l1 - m);
    const float e2 = (lane + 64 < NCLS) ? expf(l2 - m) : 0.0f;
    float s = e0 + e1 + e2;
    #pragma unroll
    for (int o = 16; o; o >>= 1) s += __shfl_xor_sync(0xffffffffu, s, o);
    const float rinv = 1.0f / s;

    const unsigned long long lowbits = (unsigned int)(NPROP - row);

    const float sc0 = e0 * rinv;
    if (lane >= 1 && sc0 >= SCORE_TH) {
        const int pos = atomicAdd(&g_cnt[lane], 1);
        g_list[lane * NMAX + pos] =
            ((unsigned long long)__float_as_uint(sc0) << 32) | lowbits;
    }
    const float sc1 = e1 * rinv;
    if (sc1 >= SCORE_TH) {
        const int c = lane + 32;
        const int pos = atomicAdd(&g_cnt[c], 1);
        g_list[c * NMAX + pos] =
            ((unsigned long long)__float_as_uint(sc1) << 32) | lowbits;
    }
    if (lane + 64 < NCLS) {
        const float sc2 = e2 * rinv;
        if (sc2 >= SCORE_TH) {
            const int c = lane + 64;
            const int pos = atomicAdd(&g_cnt[c], 1);
            g_list[c * NMAX + pos] =
                ((unsigned long long)__float_as_uint(sc2) << 32) | lowbits;
        }
    }

    if (lane == 0) {
        const float4 pr = ((const float4*)proposal)[row];
        const float w = pr.z - pr.x;
        const float h = pr.w - pr.y;
        g_prop[row] = make_float4(w, h, pr.x + 0.5f * w, pr.y + 0.5f * h);
    }
}

// ---- kernel B: per-class decode + rank sort + bitmask NMS + top-K ----
__global__ __launch_bounds__(BLK, 1)
void roi_main_kernel(const float* __restrict__ box_reg,       // [N, C*4]
                     const void*  __restrict__ p_img_h,
                     const void*  __restrict__ p_img_w,
                     float* __restrict__ out, int out_size)
{
    const int c   = blockIdx.x + 1;     // foreground class 1..90
    const int tid = threadIdx.x;

    __shared__ unsigned long long s_key[NMAX];
    __shared__ float4 s_cbox[NMAX];                // decoded boxes (compact order)
    __shared__ int    s_perm[NMAX];                // sorted pos -> compact slot
    __shared__ unsigned long long s_mask[MCAP * 4];// suppression bitmatrix
    __shared__ unsigned char s_keep[NMAX];         // fallback path only
    __shared__ int    s_list[TOPK];
    __shared__ int    s_M, s_drop, s_cnt;

    const float img_h = read_dim(p_img_h);
    const float img_w = read_dim(p_img_w);

    if (tid == 0) {
        s_M = g_cnt[c];
        g_cnt[c] = 0;        // leave clean for the next launch
        s_drop = 0;
    }
    __syncthreads();
    const int M = s_M;

    // ---- load candidate keys, decode + clip, size-filter (demote) ----
    for (int i = tid; i < M; i += BLK) {
        const unsigned long long key = g_list[c * NMAX + i];
        const int p = NPROP - (int)(unsigned int)(key & 0xffffffffULL);

        const float4 g = g_prop[p];        // w, h, cx, cy
        const float4 d = *(const float4*)(box_reg + p * (NCLS * 4) + c * 4);
        const float dx = d.x * 0.1f;
        const float dy = d.y * 0.1f;
        const float dw = fminf(d.z * 0.2f, BBOX_CLIP);
        const float dh = fminf(d.w * 0.2f, BBOX_CLIP);

        const float pcx = dx * g.x + g.z;
        const float pcy = dy * g.y + g.w;
        const float pw  = expf(dw) * g.x;
        const float ph  = expf(dh) * g.y;

        const float bx1 = fminf(fmaxf(pcx - 0.5f * pw, 0.0f), img_w);
        const float by1 = fminf(fmaxf(pcy - 0.5f * ph, 0.0f), img_h);
        const float bx2 = fminf(fmaxf(pcx + 0.5f * pw, 0.0f), img_w);
        const float by2 = fminf(fmaxf(pcy + 0.5f * ph, 0.0f), img_h);

        s_cbox[i] = make_float4(bx1, by1, bx2, by2);
        if (bx2 - bx1 < MIN_SIZE || by2 - by1 < MIN_SIZE) {
            // demote: score bits 0, unique low word -> sinks below all valid keys
            s_key[i] = key & 0xffffffffULL;
            atomicAdd(&s_drop, 1);
        } else {
            s_key[i] = key;
        }
    }
    __syncthreads();

    const int Meff = M - s_drop;

    // ---- rank sort (keys unique -> ranks are a bijection) ----
    for (int i = tid; i < M; i += BLK) {
        const unsigned long long ki = s_key[i];
        int r = 0;
        for (int j = 0; j < M; ++j) r += (s_key[j] > ki);
        s_perm[r] = i;
    }
    __syncthreads();

    const bool fast = (Meff <= MCAP);

    if (fast) {
        // ---- suppression bitmatrix over sorted positions (4 words/row) ----
        for (int t = tid; t < Meff * 4; t += BLK) {
            const int i = t >> 2;
            const int w = t & 3;
            unsigned long long bits = 0ULL;
            const int jbase = w << 6;
            const int jend  = min(jbase + 64, Meff);
            if (jend > i + 1) {
                const float4 a = s_cbox[s_perm[i]];
                const float area_a = (a.z - a.x) * (a.w - a.y);
                for (int j = max(jbase, i + 1); j < jend; ++j) {
                    const float4 b = s_cbox[s_perm[j]];
                    const float area_b = (b.z - b.x) * (b.w - b.y);
                    const float iw = fmaxf(fminf(a.z, b.z) - fmaxf(a.x, b.x), 0.0f);
                    const float ih = fmaxf(fminf(a.w, b.w) - fmaxf(a.y, b.y), 0.0f);
                    const float inter = iw * ih;
                    const float uni   = fmaxf(area_a + area_b - inter, 1e-6f);
                    if (inter > NMS_TH * uni) bits |= 1ULL << (j - jbase);
                }
            }
            s_mask[t] = bits;
        }
        __syncthreads();

        // ---- serial greedy scan: jump directly to next kept via ffs ----
        if (tid == 0) {
            unsigned long long rem0 = 0, rem1 = 0, rem2 = 0, rem3 = 0;
            int cnt = 0;
            const int nw = (Meff + 63) >> 6;
            for (int w = 0; w < nw && cnt < TOPK; ++w) {
                unsigned long long rw = (w == 0) ? rem0 : (w == 1) ? rem1
                                      : (w == 2) ? rem2 : rem3;
                unsigned long long avail = ~rw;
                if ((w << 6) + 64 > Meff)
                    avail &= (1ULL << (Meff & 63)) - 1ULL;   // Meff&63 != 0 here
                while (avail && cnt < TOPK) {
                    const int b = __ffsll((long long)avail) - 1;
                    const int i = (w << 6) + b;
                    s_list[cnt++] = i;
                    rem0 |= s_mask[i * 4 + 0];
                    rem1 |= s_mask[i * 4 + 1];
                    rem2 |= s_mask[i * 4 + 2];
                    rem3 |= s_mask[i * 4 + 3];
                    const unsigned long long nrw = (w == 0) ? rem0 : (w == 1) ? rem1
                                                 : (w == 2) ? rem2 : rem3;
                    avail &= ~nrw;
                    avail &= (b == 63) ? 0ULL : ~((2ULL << b) - 1ULL);
                }
            }
            s_cnt = cnt;
        }
        __syncthreads();
    } else {
        // ---- fallback: barrier-per-round NMS over sorted order (any M) ----
        for (int i = tid; i < Meff; i += BLK) s_keep[i] = 1;
        __syncthreads();
        for (int i = 0; i < Meff - 1; ++i) {
            if (!s_keep[i]) continue;
            const float4 a = s_cbox[s_perm[i]];
            const float area_a = (a.z - a.x) * (a.w - a.y);
            for (int j = i + 1 + tid; j < Meff; j += BLK) {
                if (!s_keep[j]) continue;
                const float4 b = s_cbox[s_perm[j]];
                const float area_b = (b.z - b.x) * (b.w - b.y);
                const float iw = fmaxf(fminf(a.z, b.z) - fmaxf(a.x, b.x), 0.0f);
                const float ih = fmaxf(fminf(a.w, b.w) - fmaxf(a.y, b.y), 0.0f);
                const float inter = iw * ih;
                const float uni   = fmaxf(area_a + area_b - inter, 1e-6f);
                if (inter > NMS_TH * uni) s_keep[j] = 0;
            }
            __syncthreads();
        }
        if (tid == 0) {
            int cnt = 0;
            for (int i = 0; i < Meff && cnt < TOPK; ++i)
                if (s_keep[i]) s_list[cnt++] = i;
            s_cnt = cnt;
        }
        __syncthreads();
    }

    // ---- write output: dets [9000,5] then labels [9000] (as float) ----
    if (tid < TOPK) {
        const int r = (c - 1) * TOPK + tid;
        float b0 = 0.f, b1 = 0.f, b2 = 0.f, b3 = 0.f, sc = 0.f, lab = 0.f;
        if (tid < s_cnt) {
            const int slot = s_perm[s_list[tid]];
            const float4 b = s_cbox[slot];
            b0 = b.x; b1 = b.y; b2 = b.z; b3 = b.w;
            sc = __uint_as_float((unsigned int)(s_key[slot] >> 32));
            lab = (float)c;
        }
        out[r * 5 + 0] = b0;
        out[r * 5 + 1] = b1;
        out[r * 5 + 2] = b2;
        out[r * 5 + 3] = b3;
        out[r * 5 + 4] = sc;
        const int dets_elems = (NCLS - 1) * TOPK * 5;        // 45000
        if (out_size >= dets_elems + (NCLS - 1) * TOPK)
            out[dets_elems + r] = lab;
    }
}

extern "C" void kernel_launch(void* const* d_in, const int* in_sizes, int n_in,
                              void* d_out, int out_size)
{
    const float* class_logit = (const float*)d_in[0];
    const float* box_reg     = (const float*)d_in[1];
    const float* proposal    = (const float*)d_in[2];
    const void*  img_h       = d_in[3];
    const void*  img_w       = d_in[4];
    (void)in_sizes; (void)n_in;

    filter_kernel<<<(NPROP * 32 + 255) / 256, 256>>>(class_logit, proposal);
    roi_main_kernel<<<NCLS - 1, BLK>>>(box_reg, img_h, img_w,
                                       (float*)d_out, out_size);
}

// round 8
// speedup vs baseline: 1.1380x; 1.1380x over previous
#include <cuda_runtime.h>
#include <math.h>

#define NPROP 1000
#define NCLS  91
#define TOPK  100
#define NMAX  1024
#define MCAP  256          /* fast bitmask-NMS path capacity */
#define BLK   256
#define GRID  (NCLS - 1)   /* 90 blocks, one per foreground class */
#define SCORE_TH 0.05f
#define NMS_TH   0.5f
#define MIN_SIZE 1.0f
#define BBOX_CLIP 4.1351665567423f   /* log(1000/16) */

// scratch (device globals; zero-init at module load)
__device__ float2 g_stats[NPROP];                 // per-row (max, 1/sum_exp)
__device__ float4 g_prop[NPROP];                  // per-row (w, h, cx, cy)
__device__ unsigned long long g_done;             // monotonic epoch ticket counter

__device__ __forceinline__ float read_dim(const void* p) {
    int iv = *(const int*)p;
    if (iv >= 1 && iv <= 100000) return (float)iv;        // int32 / int64 low word
    float fv = __int_as_float(iv);
    if (fv >= 1.0f && fv <= 100000.0f) return fv;          // float32
    return (float)iv;
}

__global__ __launch_bounds__(BLK, 1)
void roi_fused_kernel(const float* __restrict__ class_logit,   // [N, C]
                      const float* __restrict__ box_reg,       // [N, C*4]
                      const float* __restrict__ proposal,      // [N, 4]
                      const void*  __restrict__ p_img_h,
                      const void*  __restrict__ p_img_w,
                      float* __restrict__ out, int out_size)
{
    const int c    = blockIdx.x + 1;    // foreground class 1..90
    const int tid  = threadIdx.x;
    const int wid  = tid >> 5;
    const int lane = tid & 31;

    __shared__ unsigned long long s_key[NMAX];
    __shared__ float4 s_cbox[NMAX];                // decoded boxes (compact order)
    __shared__ int    s_perm[NMAX];                // sorted pos -> compact slot
    __shared__ int    s_p[NMAX];                   // compact slot -> proposal idx
    __shared__ unsigned long long s_mask[MCAP * 4];// suppression bitmatrix
    __shared__ unsigned char s_keep[NMAX];         // fallback path only
    __shared__ int    s_list[TOPK];
    __shared__ int    s_mcnt, s_drop, s_cnt;

    const float img_h = read_dim(p_img_h);
    const float img_w = read_dim(p_img_w);

    // ================= phase S: softmax stats for rows p ≡ blockIdx.x (mod 90) ====
    // warp w of round k handles row = blockIdx.x + (w + 8*k)*90; k=0,1 covers all.
    #pragma unroll
    for (int k = 0; k < 2; ++k) {
        const int row = blockIdx.x + (wid + 8 * k) * GRID;
        if (row < NPROP) {
            const float* r = class_logit + row * NCLS;
            const float l0 = r[lane];
            const float l1 = r[lane + 32];
            const float l2 = (lane + 64 < NCLS) ? r[lane + 64] : -3.4e38f;
            float m = fmaxf(l0, fmaxf(l1, l2));
            #pragma unroll
            for (int o = 16; o; o >>= 1) m = fmaxf(m, __shfl_xor_sync(0xffffffffu, m, o));
            float s = expf(l0 - m) + expf(l1 - m)
                    + ((lane + 64 < NCLS) ? expf(l2 - m) : 0.0f);
            #pragma unroll
            for (int o = 16; o; o >>= 1) s += __shfl_xor_sync(0xffffffffu, s, o);
            if (lane == 0) {
                g_stats[row] = make_float2(m, 1.0f / s);
                const float4 pr = ((const float4*)proposal)[row];
                const float w = pr.z - pr.x;
                const float h = pr.w - pr.y;
                g_prop[row] = make_float4(w, h, pr.x + 0.5f * w, pr.y + 0.5f * h);
            }
        }
    }
    __syncthreads();

    // ================= device-wide epoch barrier (replay-safe, no reset) =========
    if (tid == 0) {
        s_mcnt = 0; s_drop = 0;
        __threadfence();                                   // release stats
        const unsigned long long t = atomicAdd(&g_done, 1ULL);
        const unsigned long long target = (t / GRID) * GRID + GRID;
        while (*(volatile unsigned long long*)&g_done < target) { }
        __threadfence();                                   // acquire
    }
    __syncthreads();

    // ================= phase 1: score filter + compact ===========================
    for (int p = tid; p < NPROP; p += BLK) {
        const float  lc = __ldcg(class_logit + p * NCLS + c);
        const float2 st = __ldcg(&g_stats[p]);
        const float  score = expf(lc - st.x) * st.y;
        if (score >= SCORE_TH) {
            const int slot = atomicAdd(&s_mcnt, 1);
            s_p[slot]   = p;
            s_key[slot] = ((unsigned long long)__float_as_uint(score) << 32)
                        | (unsigned int)(NPROP - p);
        }
    }
    __syncthreads();

    const int M = s_mcnt;

    // ================= phase 2: decode + clip survivors ==========================
    for (int i = tid; i < M; i += BLK) {
        const int p = s_p[i];
        const float4 g = __ldcg(&g_prop[p]);      // w, h, cx, cy
        const float4 d = *(const float4*)(box_reg + p * (NCLS * 4) + c * 4);
        const float dx = d.x * 0.1f;
        const float dy = d.y * 0.1f;
        const float dw = fminf(d.z * 0.2f, BBOX_CLIP);
        const float dh = fminf(d.w * 0.2f, BBOX_CLIP);

        const float pcx = dx * g.x + g.z;
        const float pcy = dy * g.y + g.w;
        const float pw  = expf(dw) * g.x;
        const float ph  = expf(dh) * g.y;

        const float bx1 = fminf(fmaxf(pcx - 0.5f * pw, 0.0f), img_w);
        const float by1 = fminf(fmaxf(pcy - 0.5f * ph, 0.0f), img_h);
        const float bx2 = fminf(fmaxf(pcx + 0.5f * pw, 0.0f), img_w);
        const float by2 = fminf(fmaxf(pcy + 0.5f * ph, 0.0f), img_h);

        s_cbox[i] = make_float4(bx1, by1, bx2, by2);
        if (bx2 - bx1 < MIN_SIZE || by2 - by1 < MIN_SIZE) {
            // demote: score bits 0, unique low word -> sinks below all valid keys
            s_key[i] = (unsigned long long)(unsigned int)(NPROP - p);
            atomicAdd(&s_drop, 1);
        }
    }
    __syncthreads();

    const int Meff = M - s_drop;

    // ================= phase 3: rank sort (unique keys -> bijection) =============
    for (int i = tid; i < M; i += BLK) {
        const unsigned long long ki = s_key[i];
        int r = 0;
        for (int j = 0; j < M; ++j) r += (s_key[j] > ki);
        s_perm[r] = i;
    }
    __syncthreads();

    const bool fast = (Meff <= MCAP);

    if (fast) {
        // ---- suppression bitmatrix over sorted positions (4 words/row) ----
        for (int t = tid; t < Meff * 4; t += BLK) {
            const int i = t >> 2;
            const int w = t & 3;
            unsigned long long bits = 0ULL;
            const int jbase = w << 6;
            const int jend  = min(jbase + 64, Meff);
            if (jend > i + 1) {
                const float4 a = s_cbox[s_perm[i]];
                const float area_a = (a.z - a.x) * (a.w - a.y);
                for (int j = max(jbase, i + 1); j < jend; ++j) {
                    const float4 b = s_cbox[s_perm[j]];
                    const float area_b = (b.z - b.x) * (b.w - b.y);
                    const float iw = fmaxf(fminf(a.z, b.z) - fmaxf(a.x, b.x), 0.0f);
                    const float ih = fmaxf(fminf(a.w, b.w) - fmaxf(a.y, b.y), 0.0f);
                    const float inter = iw * ih;
                    const float uni   = fmaxf(area_a + area_b - inter, 1e-6f);
                    if (inter > NMS_TH * uni) bits |= 1ULL << (j - jbase);
                }
            }
            s_mask[t] = bits;
        }
        __syncthreads();

        // ---- serial greedy scan: jump directly to next kept via ffs ----
        if (tid == 0) {
            unsigned long long rem0 = 0, rem1 = 0, rem2 = 0, rem3 = 0;
            int cnt = 0;
            const int nw = (Meff + 63) >> 6;
            for (int w = 0; w < nw && cnt < TOPK; ++w) {
                unsigned long long rw = (w == 0) ? rem0 : (w == 1) ? rem1
                                      : (w == 2) ? rem2 : rem3;
                unsigned long long avail = ~rw;
                if ((w << 6) + 64 > Meff)
                    avail &= (1ULL << (Meff & 63)) - 1ULL;   // Meff&63 != 0 here
                while (avail && cnt < TOPK) {
                    const int b = __ffsll((long long)avail) - 1;
                    const int i = (w << 6) + b;
                    s_list[cnt++] = i;
                    rem0 |= s_mask[i * 4 + 0];
                    rem1 |= s_mask[i * 4 + 1];
                    rem2 |= s_mask[i * 4 + 2];
                    rem3 |= s_mask[i * 4 + 3];
                    const unsigned long long nrw = (w == 0) ? rem0 : (w == 1) ? rem1
                                                 : (w == 2) ? rem2 : rem3;
                    avail &= ~nrw;
                    avail &= (b == 63) ? 0ULL : ~((2ULL << b) - 1ULL);
                }
            }
            s_cnt = cnt;
        }
        __syncthreads();
    } else {
        // ---- fallback: barrier-per-round NMS over sorted order (any M) ----
        for (int i = tid; i < Meff; i += BLK) s_keep[i] = 1;
        __syncthreads();
        for (int i = 0; i < Meff - 1; ++i) {
            if (!s_keep[i]) continue;
            const float4 a = s_cbox[s_perm[i]];
            const float area_a = (a.z - a.x) * (a.w - a.y);
            for (int j = i + 1 + tid; j < Meff; j += BLK) {
                if (!s_keep[j]) continue;
                const float4 b = s_cbox[s_perm[j]];
                const float area_b = (b.z - b.x) * (b.w - b.y);
                const float iw = fmaxf(fminf(a.z, b.z) - fmaxf(a.x, b.x), 0.0f);
                const float ih = fmaxf(fminf(a.w, b.w) - fmaxf(a.y, b.y), 0.0f);
                const float inter = iw * ih;
                const float uni   = fmaxf(area_a + area_b - inter, 1e-6f);
                if (inter > NMS_TH * uni) s_keep[j] = 0;
            }
            __syncthreads();
        }
        if (tid == 0) {
            int cnt = 0;
            for (int i = 0; i < Meff && cnt < TOPK; ++i)
                if (s_keep[i]) s_list[cnt++] = i;
            s_cnt = cnt;
        }
        __syncthreads();
    }

    // ================= output: dets [9000,5] then labels [9000] (as float) =======
    if (tid < TOPK) {
        const int r = (c - 1) * TOPK + tid;
        float b0 = 0.f, b1 = 0.f, b2 = 0.f, b3 = 0.f, sc = 0.f, lab = 0.f;
        if (tid < s_cnt) {
            const int slot = s_perm[s_list[tid]];
            const float4 b = s_cbox[slot];
            b0 = b.x; b1 = b.y; b2 = b.z; b3 = b.w;
            sc = __uint_as_float((unsigned int)(s_key[slot] >> 32));
            lab = (float)c;
        }
        out[r * 5 + 0] = b0;
        out[r * 5 + 1] = b1;
        out[r * 5 + 2] = b2;
        out[r * 5 + 3] = b3;
        out[r * 5 + 4] = sc;
        const int dets_elems = (NCLS - 1) * TOPK * 5;        // 45000
        if (out_size >= dets_elems + (NCLS - 1) * TOPK)
            out[dets_elems + r] = lab;
    }
}

extern "C" void kernel_launch(void* const* d_in, const int* in_sizes, int n_in,
                              void* d_out, int out_size)
{
    const float* class_logit = (const float*)d_in[0];
    const float* box_reg     = (const float*)d_in[1];
    const float* proposal    = (const float*)d_in[2];
    const void*  img_h       = d_in[3];
    const void*  img_w       = d_in[4];
    (void)in_sizes; (void)n_in;

    roi_fused_kernel<<<GRID, BLK>>>(class_logit, box_reg, proposal,
                                    img_h, img_w,
                                    (float*)d_out, out_size);
}

// round 9
// speedup vs baseline: 1.3400x; 1.1775x over previous
#include <cuda_runtime.h>
#include <math.h>

#define NPROP 1000
#define NCLS  91
#define TOPK  100
#define NMAX  1024
#define MCAP  256          /* fast bitmask-NMS path capacity */
#define BLK   256
#define GRID  (NCLS - 1)
#define SCORE_TH 0.05f
#define NMS_TH   0.5f
#define MIN_SIZE 1.0f
#define BBOX_CLIP 4.1351665567423f   /* log(1000/16) */

// scratch: per-row softmax stats (max, 1/sum_exp) and proposal geometry (w,h,cx,cy)
__device__ float2 g_stats[NPROP];
__device__ float4 g_prop[NPROP];

__device__ __forceinline__ float read_dim(const void* p) {
    int iv = *(const int*)p;
    if (iv >= 1 && iv <= 100000) return (float)iv;        // int32 / int64 low word
    float fv = __int_as_float(iv);
    if (fv >= 1.0f && fv <= 100000.0f) return fv;          // float32
    return (float)iv;
}

// ------------- kernel A: per-row softmax stats + proposal geometry -------------
__global__ void softmax_stats_kernel(const float* __restrict__ class_logit,
                                     const float* __restrict__ proposal)
{
    const int gtid = blockIdx.x * blockDim.x + threadIdx.x;
    const int row  = gtid >> 5;
    const int lane = gtid & 31;
    if (row < NPROP) {
        const float* r = class_logit + row * NCLS;
        const float l0 = r[lane];
        const float l1 = r[lane + 32];
        const float l2 = (lane + 64 < NCLS) ? r[lane + 64] : -3.4e38f;

        float m = fmaxf(l0, fmaxf(l1, l2));
        #pragma unroll
        for (int o = 16; o; o >>= 1) m = fmaxf(m, __shfl_xor_sync(0xffffffffu, m, o));

        float s = expf(l0 - m) + expf(l1 - m)
                + ((lane + 64 < NCLS) ? expf(l2 - m) : 0.0f);
        #pragma unroll
        for (int o = 16; o; o >>= 1) s += __shfl_xor_sync(0xffffffffu, s, o);

        if (lane == 0) {
            g_stats[row] = make_float2(m, 1.0f / s);
            const float4 pr = ((const float4*)proposal)[row];
            const float w = pr.z - pr.x;
            const float h = pr.w - pr.y;
            g_prop[row] = make_float4(w, h, pr.x + 0.5f * w, pr.y + 0.5f * h);
        }
    }
    __threadfence();
#if __CUDA_ARCH__ >= 900
    cudaTriggerProgrammaticLaunchCompletion();
#endif
}

// ---- kernel B: per-class score-filter + decode + rank sort + NMS + top-K ----
__global__ __launch_bounds__(BLK, 1)
void roi_main_kernel(const float* __restrict__ class_logit,   // [N, C]
                     const float* __restrict__ box_reg,       // [N, C*4]
                     const void*  __restrict__ p_img_h,
                     const void*  __restrict__ p_img_w,
                     float* __restrict__ out, int out_size)
{
    const int c   = blockIdx.x + 1;     // foreground class 1..90
    const int tid = threadIdx.x;

    __shared__ unsigned long long s_key[NMAX];
    __shared__ float4 s_cbox[NMAX];                // decoded boxes (compact order)
    __shared__ int    s_perm[NMAX];                // sorted pos -> compact slot
    __shared__ unsigned long long s_mask[MCAP * 4];// suppression bitmatrix
    __shared__ unsigned char s_keep[NMAX];         // fallback path only
    __shared__ int    s_list[TOPK];
    __shared__ int    s_mcnt, s_drop, s_cnt;

    const float img_h = read_dim(p_img_h);
    const float img_w = read_dim(p_img_w);

    if (tid == 0) { s_mcnt = 0; s_drop = 0; }
    __syncthreads();

#if __CUDA_ARCH__ >= 900
    cudaGridDependencySynchronize();    // wait for kernel A's stats
#endif

    // ---- phase 1: score filter + inline decode + compact ----
    for (int p = tid; p < NPROP; p += BLK) {
        const float  lc = class_logit[p * NCLS + c];
        const float2 st = g_stats[p];
        const float  score = expf(lc - st.x) * st.y;
        if (score >= SCORE_TH) {
            const int slot = atomicAdd(&s_mcnt, 1);

            const float4 g = g_prop[p];        // w, h, cx, cy
            const float4 d = *(const float4*)(box_reg + p * (NCLS * 4) + c * 4);
            const float dx = d.x * 0.1f;
            const float dy = d.y * 0.1f;
            const float dw = fminf(d.z * 0.2f, BBOX_CLIP);
            const float dh = fminf(d.w * 0.2f, BBOX_CLIP);

            const float pcx = dx * g.x + g.z;
            const float pcy = dy * g.y + g.w;
            const float pw  = expf(dw) * g.x;
            const float ph  = expf(dh) * g.y;

            const float bx1 = fminf(fmaxf(pcx - 0.5f * pw, 0.0f), img_w);
            const float by1 = fminf(fmaxf(pcy - 0.5f * ph, 0.0f), img_h);
            const float bx2 = fminf(fmaxf(pcx + 0.5f * pw, 0.0f), img_w);
            const float by2 = fminf(fmaxf(pcy + 0.5f * ph, 0.0f), img_h);

            s_cbox[slot] = make_float4(bx1, by1, bx2, by2);
            if (bx2 - bx1 < MIN_SIZE || by2 - by1 < MIN_SIZE) {
                // demote: score bits 0, unique low word -> sinks below all valid
                s_key[slot] = (unsigned long long)(unsigned int)(NPROP - p);
                atomicAdd(&s_drop, 1);
            } else {
                s_key[slot] = ((unsigned long long)__float_as_uint(score) << 32)
                            | (unsigned int)(NPROP - p);
            }
        }
    }
    __syncthreads();

    const int M    = s_mcnt;
    const int Meff = M - s_drop;

    // ---- rank sort (keys unique -> ranks are a bijection) ----
    for (int i = tid; i < M; i += BLK) {
        const unsigned long long ki = s_key[i];
        int r = 0;
        for (int j = 0; j < M; ++j) r += (s_key[j] > ki);
        s_perm[r] = i;
    }
    __syncthreads();

    const bool fast = (Meff <= MCAP);

    if (fast) {
        // ---- suppression bitmatrix over sorted positions (4 words/row) ----
        for (int t = tid; t < Meff * 4; t += BLK) {
            const int i = t >> 2;
            const int w = t & 3;
            unsigned long long bits = 0ULL;
            const int jbase = w << 6;
            const int jend  = min(jbase + 64, Meff);
            if (jend > i + 1) {
                const float4 a = s_cbox[s_perm[i]];
                const float area_a = (a.z - a.x) * (a.w - a.y);
                for (int j = max(jbase, i + 1); j < jend; ++j) {
                    const float4 b = s_cbox[s_perm[j]];
                    const float area_b = (b.z - b.x) * (b.w - b.y);
                    const float iw = fmaxf(fminf(a.z, b.z) - fmaxf(a.x, b.x), 0.0f);
                    const float ih = fmaxf(fminf(a.w, b.w) - fmaxf(a.y, b.y), 0.0f);
                    const float inter = iw * ih;
                    const float uni   = fmaxf(area_a + area_b - inter, 1e-6f);
                    if (inter > NMS_TH * uni) bits |= 1ULL << (j - jbase);
                }
            }
            s_mask[t] = bits;
        }
        __syncthreads();

        // ---- serial greedy scan: ffs-jump to next kept; 128-bit mask loads ----
        if (tid == 0) {
            unsigned long long rem0 = 0, rem1 = 0, rem2 = 0, rem3 = 0;
            int cnt = 0;
            const int nw = (Meff + 63) >> 6;
            const ulonglong2* mrows = (const ulonglong2*)s_mask;
            for (int w = 0; w < nw && cnt < TOPK; ++w) {
                unsigned long long rw = (w == 0) ? rem0 : (w == 1) ? rem1
                                      : (w == 2) ? rem2 : rem3;
                unsigned long long avail = ~rw;
                if ((w << 6) + 64 > Meff)
                    avail &= (1ULL << (Meff & 63)) - 1ULL;   // Meff&63 != 0 here
                while (avail && cnt < TOPK) {
                    const int b = __ffsll((long long)avail) - 1;
                    const int i = (w << 6) + b;
                    s_list[cnt++] = i;
                    const ulonglong2 m01 = mrows[i * 2 + 0];
                    const ulonglong2 m23 = mrows[i * 2 + 1];
                    rem0 |= m01.x; rem1 |= m01.y;
                    rem2 |= m23.x; rem3 |= m23.y;
                    const unsigned long long nrw = (w == 0) ? rem0 : (w == 1) ? rem1
                                                 : (w == 2) ? rem2 : rem3;
                    avail &= ~nrw;
                    avail &= (b == 63) ? 0ULL : ~((2ULL << b) - 1ULL);
                }
            }
            s_cnt = cnt;
        }
        __syncthreads();
    } else {
        // ---- fallback: barrier-per-round NMS over sorted order (any M) ----
        for (int i = tid; i < Meff; i += BLK) s_keep[i] = 1;
        __syncthreads();
        for (int i = 0; i < Meff - 1; ++i) {
            if (!s_keep[i]) continue;
            const float4 a = s_cbox[s_perm[i]];
            const float area_a = (a.z - a.x) * (a.w - a.y);
            for (int j = i + 1 + tid; j < Meff; j += BLK) {
                if (!s_keep[j]) continue;
                const float4 b = s_cbox[s_perm[j]];
                const float area_b = (b.z - b.x) * (b.w - b.y);
                const float iw = fmaxf(fminf(a.z, b.z) - fmaxf(a.x, b.x), 0.0f);
                const float ih = fmaxf(fminf(a.w, b.w) - fmaxf(a.y, b.y), 0.0f);
                const float inter = iw * ih;
                const float uni   = fmaxf(area_a + area_b - inter, 1e-6f);
                if (inter > NMS_TH * uni) s_keep[j] = 0;
            }
            __syncthreads();
        }
        if (tid == 0) {
            int cnt = 0;
            for (int i = 0; i < Meff && cnt < TOPK; ++i)
                if (s_keep[i]) s_list[cnt++] = i;
            s_cnt = cnt;
        }
        __syncthreads();
    }

    // ---- write output: dets [9000,5] then labels [9000] (as float) ----
    if (tid < TOPK) {
        const int r = (c - 1) * TOPK + tid;
        float b0 = 0.f, b1 = 0.f, b2 = 0.f, b3 = 0.f, sc = 0.f, lab = 0.f;
        if (tid < s_cnt) {
            const int slot = s_perm[s_list[tid]];
            const float4 b = s_cbox[slot];
            b0 = b.x; b1 = b.y; b2 = b.z; b3 = b.w;
            sc = __uint_as_float((unsigned int)(s_key[slot] >> 32));
            lab = (float)c;
        }
        out[r * 5 + 0] = b0;
        out[r * 5 + 1] = b1;
        out[r * 5 + 2] = b2;
        out[r * 5 + 3] = b3;
        out[r * 5 + 4] = sc;
        const int dets_elems = (NCLS - 1) * TOPK * 5;        // 45000
        if (out_size >= dets_elems + (NCLS - 1) * TOPK)
            out[dets_elems + r] = lab;
    }
}

extern "C" void kernel_launch(void* const* d_in, const int* in_sizes, int n_in,
                              void* d_out, int out_size)
{
    const float* class_logit = (const float*)d_in[0];
    const float* box_reg     = (const float*)d_in[1];
    const float* proposal    = (const float*)d_in[2];
    const void*  img_h       = d_in[3];
    const void*  img_w       = d_in[4];
    (void)in_sizes; (void)n_in;

    softmax_stats_kernel<<<(NPROP * 32 + 255) / 256, 256>>>(class_logit, proposal);

    // kernel B with programmatic dependent launch: overlap its launch with A
    cudaLaunchConfig_t cfg = {};
    cfg.gridDim  = dim3(GRID, 1, 1);
    cfg.blockDim = dim3(BLK, 1, 1);
    cfg.dynamicSmemBytes = 0;
    cfg.stream = 0;
    cudaLaunchAttribute attr[1];
    attr[0].id = cudaLaunchAttributeProgrammaticStreamSerialization;
    attr[0].val.programmaticStreamSerializationAllowed = 1;
    cfg.attrs = attr;
    cfg.numAttrs = 1;

    float* outp = (float*)d_out;
    cudaLaunchKernelEx(&cfg, roi_main_kernel,
                       class_logit, box_reg,
                       (const void*)img_h, (const void*)img_w,
                       outp, out_size);
}